// round 1
// baseline (speedup 1.0000x reference)
#include <cuda_runtime.h>
#include <cstdint>

#define N_MAX 50176

// Scratch + precomputed vectors (no allocation allowed -> __device__ globals)
__device__ float g_agg[(size_t)N_MAX * 128];   // attention-weighted neigh_feat rows
__device__ float g_wa[128];                    // W  @ a[0:64]
__device__ float g_w2a[128];                   // W2 @ a[64:128]

// ---------------------------------------------------------------------------
// Prep: fold attention vectors through the weight matrices.
// ---------------------------------------------------------------------------
__global__ void prep_kernel(const float* __restrict__ W,
                            const float* __restrict__ W2,
                            const float* __restrict__ a)
{
    int d = threadIdx.x;              // 0..127
    float s1 = 0.f, s2 = 0.f;
#pragma unroll
    for (int j = 0; j < 64; ++j) {
        s1 += W [d * 64 + j] * a[j];
        s2 += W2[d * 64 + j] * a[64 + j];
    }
    g_wa[d]  = s1;
    g_w2a[d] = s2;
}

// ---------------------------------------------------------------------------
// Kernel A: per-node attention (scores -> leaky relu -> softmax) and
// aggregation. One warp per node, 8 nodes per 256-thread block.
// neigh_feat row block (16x128) staged once in SMEM, reused twice.
// Writes g_agg (N x 128) and out[:, 128:160] (h_edge).
// ---------------------------------------------------------------------------
__global__ void attn_kernel(const float* __restrict__ input,
                            const float* __restrict__ neigh,
                            const float* __restrict__ edge,
                            const float* __restrict__ a,
                            float* __restrict__ out, int N)
{
    extern __shared__ float sm[];
    float* s_w2a = sm;            // 128
    float* s_ae  = sm + 128;      // 32
    float* wbase = sm + 160;      // 8 warps x (2048 + 512 + 16)

    const int tid = threadIdx.x;
    const int wid = tid >> 5;
    const int lid = tid & 31;

    if (tid < 128) s_w2a[tid] = g_w2a[tid];
    if (tid < 32)  s_ae[tid]  = a[128 + tid];

    float* sn = wbase + wid * 2576;   // 16 x 128 neigh tile
    float* se = sn + 2048;            // 16 x 32  edge tile
    float* sa = se + 512;             // 16 attention weights
    __syncthreads();

    const int n = blockIdx.x * 8 + wid;
    if (n >= N) return;

    // ---- stage neigh (16x128) and edge (16x32) tiles, fully coalesced ----
    const float4* nsrc = (const float4*)(neigh + (size_t)n * 2048);
    float4*       ndst = (float4*)sn;
#pragma unroll
    for (int i = 0; i < 16; ++i) ndst[lid + 32 * i] = nsrc[lid + 32 * i];

    const float4* esrc = (const float4*)(edge + (size_t)n * 512);
    float4*       edst = (float4*)se;
#pragma unroll
    for (int i = 0; i < 4; ++i)  edst[lid + 32 * i] = esrc[lid + 32 * i];

    // ---- s_x = input[n] . (W @ a_x), full-warp reduction ----
    float sx = 0.f;
#pragma unroll
    for (int k = 0; k < 4; ++k) {
        int d = lid + 32 * k;
        sx += input[(size_t)n * 128 + d] * g_wa[d];
    }
#pragma unroll
    for (int o = 16; o; o >>= 1) sx += __shfl_xor_sync(0xffffffffu, sx, o);

    __syncwarp();

    // ---- scores: lane (s = lid&15, h = lid>>4) covers half the dims ----
    const int s = lid & 15, h = lid >> 4;
    const float* nrow = sn + s * 128 + h * 64;
    float part = 0.f;
    const int o0 = (s * 2 + h) & 63;          // stagger -> conflict-free banks
#pragma unroll
    for (int i = 0; i < 64; ++i) {
        int d = (o0 + i) & 63;
        part += nrow[d] * s_w2a[h * 64 + d];
    }
    const float* erow = se + s * 32 + h * 16;
#pragma unroll
    for (int i = 0; i < 16; ++i) {
        int j = (s + i) & 15;
        part += erow[j] * s_ae[h * 16 + j];
    }
    part += __shfl_xor_sync(0xffffffffu, part, 16);   // combine halves

    float sc = sx + part;
    float ev = sc > 0.f ? sc : 0.8f * sc;             // leaky relu, ALPHA=0.8

    // softmax over the 16 s-values (each duplicated in both 16-lane halves)
    float mx = ev;
#pragma unroll
    for (int of = 8; of; of >>= 1) mx = fmaxf(mx, __shfl_xor_sync(0xffffffffu, mx, of));
    float p = __expf(ev - mx);
    float sum = p;
#pragma unroll
    for (int of = 8; of; of >>= 1) sum += __shfl_xor_sync(0xffffffffu, sum, of);
    float att = p / sum;
    if (h == 0) sa[s] = att;
    __syncwarp();

    // ---- aggregation: agg[n, d] = sum_s att[s] * neigh[n, s, d] ----
    float acc0 = 0.f, acc1 = 0.f, acc2 = 0.f, acc3 = 0.f;
#pragma unroll
    for (int ss = 0; ss < 16; ++ss) {
        float at = sa[ss];
        const float* r = sn + ss * 128 + lid;
        acc0 += at * r[0];
        acc1 += at * r[32];
        acc2 += at * r[64];
        acc3 += at * r[96];
    }
    float* ag = g_agg + (size_t)n * 128 + lid;
    ag[0]  = acc0;  ag[32] = acc1;  ag[64] = acc2;  ag[96] = acc3;

    // ---- h_edge -> out[:, 128:160] directly ----
    float eacc = 0.f;
#pragma unroll
    for (int ss = 0; ss < 16; ++ss) eacc += sa[ss] * se[ss * 32 + lid];
    out[(size_t)n * 160 + 128 + lid] = eacc;
}

// ---------------------------------------------------------------------------
// Kernel B: two N x 64 = (N x 128) @ (128 x 64) fp32 GEMMs.
//   blockIdx.y == 0 : input  @ W   -> out cols [0, 64)
//   blockIdx.y == 1 : g_agg  @ W2  -> out cols [64, 128)
// 128 threads, tile 128 rows x 64 cols, 8x8 register tile per thread.
// A staged as [row][129] (conflict-free), W as [k][64].
// ---------------------------------------------------------------------------
__global__ void gemm_kernel(const float* __restrict__ input,
                            const float* __restrict__ W,
                            const float* __restrict__ W2,
                            float* __restrict__ out, int N)
{
    extern __shared__ float sm[];
    float* sA = sm;               // 128 * 129
    float* sW = sm + 128 * 129;   // 128 * 64

    const int tid  = threadIdx.x;          // 128 threads
    const int row0 = blockIdx.x * 128;
    const bool second = (blockIdx.y != 0);

    const float* A  = second ? g_agg : input;
    const float* Wm = second ? W2    : W;
    const int coff  = second ? 64    : 0;

    // stage A tile (128 rows x 128 k) as [row][129]
    {
        const float4* A4 = (const float4*)A;
#pragma unroll
        for (int it = 0; it < 32; ++it) {
            int idx = it * 128 + tid;        // float4 index, 0..4095
            int row = idx >> 5;
            int k4  = idx & 31;
            float4 v = make_float4(0.f, 0.f, 0.f, 0.f);
            if (row0 + row < N) v = A4[(size_t)(row0 + row) * 32 + k4];
            float* d = sA + row * 129 + k4 * 4;
            d[0] = v.x; d[1] = v.y; d[2] = v.z; d[3] = v.w;
        }
    }
    // stage W (128 x 64)
    {
        const float4* W4 = (const float4*)Wm;
        float4*       s4 = (float4*)sW;
#pragma unroll
        for (int it = 0; it < 16; ++it) s4[it * 128 + tid] = W4[it * 128 + tid];
    }
    __syncthreads();

    const int rb = (tid >> 3) * 8;   // row base: 0..120
    const int cb = (tid & 7) * 8;    // col base: 0..56

    float acc[8][8];
#pragma unroll
    for (int r = 0; r < 8; ++r)
#pragma unroll
        for (int c = 0; c < 8; ++c) acc[r][c] = 0.f;

#pragma unroll 4
    for (int k = 0; k < 128; ++k) {
        float av[8];
#pragma unroll
        for (int r = 0; r < 8; ++r) av[r] = sA[(rb + r) * 129 + k];
        float4 w0 = *(const float4*)&sW[k * 64 + cb];
        float4 w1 = *(const float4*)&sW[k * 64 + cb + 4];
        float wv[8] = {w0.x, w0.y, w0.z, w0.w, w1.x, w1.y, w1.z, w1.w};
#pragma unroll
        for (int r = 0; r < 8; ++r)
#pragma unroll
            for (int c = 0; c < 8; ++c) acc[r][c] += av[r] * wv[c];
    }

#pragma unroll
    for (int r = 0; r < 8; ++r) {
        int row = row0 + rb + r;
        if (row < N) {
            float* dst = out + (size_t)row * 160 + coff + cb;
            *(float4*)dst       = make_float4(acc[r][0], acc[r][1], acc[r][2], acc[r][3]);
            *(float4*)(dst + 4) = make_float4(acc[r][4], acc[r][5], acc[r][6], acc[r][7]);
        }
    }
}

// ---------------------------------------------------------------------------
extern "C" void kernel_launch(void* const* d_in, const int* in_sizes, int n_in,
                              void* d_out, int out_size)
{
    const float* input = (const float*)d_in[0];
    const float* neigh = (const float*)d_in[1];
    const float* edge  = (const float*)d_in[2];
    const float* W     = (const float*)d_in[3];
    const float* W2    = (const float*)d_in[4];
    const float* a     = (const float*)d_in[5];
    float* out = (float*)d_out;

    const int N = in_sizes[0] / 128;

    // dynamic SMEM sizes
    const int smemA = (160 + 8 * 2576) * 4;                 // 83,072 B
    const int smemB = (128 * 129 + 128 * 64) * 4;           // 98,816 B
    cudaFuncSetAttribute(attn_kernel, cudaFuncAttributeMaxDynamicSharedMemorySize, smemA);
    cudaFuncSetAttribute(gemm_kernel, cudaFuncAttributeMaxDynamicSharedMemorySize, smemB);

    prep_kernel<<<1, 128>>>(W, W2, a);

    attn_kernel<<<(N + 7) / 8, 256, smemA>>>(input, neigh, edge, a, out, N);

    dim3 gb((N + 127) / 128, 2);
    gemm_kernel<<<gb, 128, smemB>>>(input, W, W2, out, N);
}

// round 2
// speedup vs baseline: 1.0370x; 1.0370x over previous
#include <cuda_runtime.h>
#include <cstdint>

#define N_MAX 50176

// Scratch + precomputed vector (no allocation allowed -> __device__ globals)
__device__ float g_agg[(size_t)N_MAX * 128];   // attention-weighted neigh_feat rows
__device__ float g_w2a[128];                   // W2 @ a[64:128]

// ---------------------------------------------------------------------------
// packed f32x2 helpers (ptxas won't auto-fuse; only reachable via PTX)
// ---------------------------------------------------------------------------
__device__ __forceinline__ unsigned long long pack2(float lo, float hi) {
    unsigned long long r;
    asm("mov.b64 %0, {%1, %2};" : "=l"(r) : "f"(lo), "f"(hi));
    return r;
}
__device__ __forceinline__ void ffma2(unsigned long long& acc,
                                      unsigned long long a,
                                      unsigned long long b) {
    asm("fma.rn.f32x2 %0, %1, %2, %0;" : "+l"(acc) : "l"(a), "l"(b));
}
__device__ __forceinline__ float2 unpack2(unsigned long long v) {
    float lo, hi;
    asm("mov.b64 {%0, %1}, %2;" : "=f"(lo), "=f"(hi) : "l"(v));
    return make_float2(lo, hi);
}

// ---------------------------------------------------------------------------
// GEMM: (N x 128) @ (128 x 64) fp32 -> out[:, coff : coff+64]
// 128 threads, tile 128 rows x 64 cols, 8x8 register tile via f32x2 FMA.
// If doW2a, block 0 additionally computes g_w2a = W2 @ a[64:128].
// ---------------------------------------------------------------------------
__global__ void gemm_kernel(const float* __restrict__ Ain,
                            const float* __restrict__ Wm,
                            const float* __restrict__ a,
                            float* __restrict__ out, int N,
                            int coff, int useAgg, int doW2a)
{
    extern __shared__ float sm[];
    float* sA = sm;               // 128 * 129
    float* sW = sm + 128 * 129;   // 128 * 64

    const int tid  = threadIdx.x;          // 128 threads
    const int row0 = blockIdx.x * 128;
    const float* A = useAgg ? (const float*)g_agg : Ain;

    if (doW2a && blockIdx.x == 0) {
        // g_w2a[d] = dot(Wm row d, a[64:128])  (Wm == W2 on this launch path
        // is NOT the case -- W2 passed separately below; here Wm is W.)
        // handled by passing W2 via Ain-slot trick is ugly; instead this flag
        // is only set on a launch where the extra pointer is supplied.
    }

    // stage A tile (128 rows x 128 k) as [row][129] (conflict-free)
    {
        const float4* A4 = (const float4*)A;
#pragma unroll
        for (int it = 0; it < 32; ++it) {
            int idx = it * 128 + tid;        // float4 index, 0..4095
            int row = idx >> 5;
            int k4  = idx & 31;
            float4 v = make_float4(0.f, 0.f, 0.f, 0.f);
            if (row0 + row < N) v = A4[(size_t)(row0 + row) * 32 + k4];
            float* d = sA + row * 129 + k4 * 4;
            d[0] = v.x; d[1] = v.y; d[2] = v.z; d[3] = v.w;
        }
    }
    // stage W (128 x 64)
    {
        const float4* W4 = (const float4*)Wm;
        float4*       s4 = (float4*)sW;
#pragma unroll
        for (int it = 0; it < 16; ++it) s4[it * 128 + tid] = W4[it * 128 + tid];
    }
    __syncthreads();

    const int rb = (tid >> 3) * 8;   // row base: 0..120
    const int cb = (tid & 7) * 8;    // col base: 0..56

    unsigned long long acc[8][4];
#pragma unroll
    for (int r = 0; r < 8; ++r)
#pragma unroll
        for (int c = 0; c < 4; ++c) acc[r][c] = 0ULL;

#pragma unroll 4
    for (int k = 0; k < 128; ++k) {
        unsigned long long av2[8];
#pragma unroll
        for (int r = 0; r < 8; ++r) {
            float av = sA[(rb + r) * 129 + k];
            av2[r] = pack2(av, av);
        }
        float4 w0 = *(const float4*)&sW[k * 64 + cb];
        float4 w1 = *(const float4*)&sW[k * 64 + cb + 4];
        unsigned long long w2[4] = { pack2(w0.x, w0.y), pack2(w0.z, w0.w),
                                     pack2(w1.x, w1.y), pack2(w1.z, w1.w) };
#pragma unroll
        for (int r = 0; r < 8; ++r)
#pragma unroll
            for (int c = 0; c < 4; ++c) ffma2(acc[r][c], av2[r], w2[c]);
    }

#pragma unroll
    for (int r = 0; r < 8; ++r) {
        int row = row0 + rb + r;
        if (row < N) {
            float* dst = out + (size_t)row * 160 + coff + cb;
            float2 p0 = unpack2(acc[r][0]), p1 = unpack2(acc[r][1]);
            float2 p2 = unpack2(acc[r][2]), p3 = unpack2(acc[r][3]);
            *(float4*)dst       = make_float4(p0.x, p0.y, p1.x, p1.y);
            *(float4*)(dst + 4) = make_float4(p2.x, p2.y, p3.x, p3.y);
        }
    }
}

// ---------------------------------------------------------------------------
// Tiny side-task fused into the first GEMM wave: g_w2a = W2 @ a_n.
// Launched as part of gemm_x by a dedicated extra block (blockIdx.x == gridDim.x-1
// would complicate tiling; instead do it in a 1-block prologue-free way here).
// ---------------------------------------------------------------------------
__global__ void w2a_kernel(const float* __restrict__ W2,
                           const float* __restrict__ a)
{
    int d = threadIdx.x;              // 0..127
    float s2 = 0.f;
#pragma unroll
    for (int j = 0; j < 64; ++j) s2 += W2[d * 64 + j] * a[64 + j];
    g_w2a[d] = s2;
}

// ---------------------------------------------------------------------------
// Kernel A: per-node attention (scores -> leaky relu -> softmax) and
// aggregation. One warp per node, 8 nodes per 256-thread block.
// Score x-term comes from out[:, 0:64] (written by gemm_x, L2-hot).
// Writes g_agg (N x 128) and out[:, 128:160] (h_edge).
// ---------------------------------------------------------------------------
__global__ void attn_kernel(const float* __restrict__ neigh,
                            const float* __restrict__ edge,
                            const float* __restrict__ a,
                            float* __restrict__ out, int N)
{
    extern __shared__ float sm[];
    float* s_w2a = sm;            // 128
    float* s_ae  = sm + 128;      // 32
    float* wbase = sm + 160;      // 8 warps x (2048 + 512 + 16)

    const int tid = threadIdx.x;
    const int wid = tid >> 5;
    const int lid = tid & 31;

    if (tid < 128) s_w2a[tid] = g_w2a[tid];
    if (tid < 32)  s_ae[tid]  = a[128 + tid];

    float* sn = wbase + wid * 2576;   // 16 x 128 neigh tile
    float* se = sn + 2048;            // 16 x 32  edge tile
    float* sa = se + 512;             // 16 attention weights
    __syncthreads();

    const int n = blockIdx.x * 8 + wid;
    if (n >= N) return;

    // ---- stage neigh (16x128) and edge (16x32) tiles, fully coalesced ----
    const float4* nsrc = (const float4*)(neigh + (size_t)n * 2048);
    float4*       ndst = (float4*)sn;
#pragma unroll
    for (int i = 0; i < 16; ++i) ndst[lid + 32 * i] = nsrc[lid + 32 * i];

    const float4* esrc = (const float4*)(edge + (size_t)n * 512);
    float4*       edst = (float4*)se;
#pragma unroll
    for (int i = 0; i < 4; ++i)  edst[lid + 32 * i] = esrc[lid + 32 * i];

    // ---- s_x = x[n] . a_x  (x = out[n, 0:64], written by gemm_x) ----
    const float* xr = out + (size_t)n * 160;
    float sx = xr[lid] * a[lid] + xr[lid + 32] * a[lid + 32];
#pragma unroll
    for (int o = 16; o; o >>= 1) sx += __shfl_xor_sync(0xffffffffu, sx, o);

    __syncwarp();

    // ---- scores: lane (s = lid&15, h = lid>>4) covers half the dims ----
    const int s = lid & 15, h = lid >> 4;
    const float* nrow = sn + s * 128 + h * 64;
    float part = 0.f;
    const int o0 = (s * 2 + h) & 63;          // stagger -> conflict-free banks
#pragma unroll
    for (int i = 0; i < 64; ++i) {
        int d = (o0 + i) & 63;
        part += nrow[d] * s_w2a[h * 64 + d];
    }
    const float* erow = se + s * 32 + h * 16;
#pragma unroll
    for (int i = 0; i < 16; ++i) {
        int j = (s + i) & 15;
        part += erow[j] * s_ae[h * 16 + j];
    }
    part += __shfl_xor_sync(0xffffffffu, part, 16);   // combine halves

    float sc = sx + part;
    float ev = sc > 0.f ? sc : 0.8f * sc;             // leaky relu, ALPHA=0.8

    // softmax over the 16 s-values (each duplicated in both 16-lane halves)
    float mx = ev;
#pragma unroll
    for (int of = 8; of; of >>= 1) mx = fmaxf(mx, __shfl_xor_sync(0xffffffffu, mx, of));
    float p = __expf(ev - mx);
    float sum = p;
#pragma unroll
    for (int of = 8; of; of >>= 1) sum += __shfl_xor_sync(0xffffffffu, sum, of);
    float att = p / sum;
    if (h == 0) sa[s] = att;
    __syncwarp();

    // ---- aggregation: agg[n, d] = sum_s att[s] * neigh[n, s, d] ----
    float acc0 = 0.f, acc1 = 0.f, acc2 = 0.f, acc3 = 0.f;
#pragma unroll
    for (int ss = 0; ss < 16; ++ss) {
        float at = sa[ss];
        const float* r = sn + ss * 128 + lid;
        acc0 += at * r[0];
        acc1 += at * r[32];
        acc2 += at * r[64];
        acc3 += at * r[96];
    }
    float* ag = g_agg + (size_t)n * 128 + lid;
    ag[0]  = acc0;  ag[32] = acc1;  ag[64] = acc2;  ag[96] = acc3;

    // ---- h_edge -> out[:, 128:160] directly ----
    float eacc = 0.f;
#pragma unroll
    for (int ss = 0; ss < 16; ++ss) eacc += sa[ss] * se[ss * 32 + lid];
    out[(size_t)n * 160 + 128 + lid] = eacc;
}

// ---------------------------------------------------------------------------
extern "C" void kernel_launch(void* const* d_in, const int* in_sizes, int n_in,
                              void* d_out, int out_size)
{
    const float* input = (const float*)d_in[0];
    const float* neigh = (const float*)d_in[1];
    const float* edge  = (const float*)d_in[2];
    const float* W     = (const float*)d_in[3];
    const float* W2    = (const float*)d_in[4];
    const float* a     = (const float*)d_in[5];
    float* out = (float*)d_out;

    const int N = in_sizes[0] / 128;

    const int smemA = (160 + 8 * 2576) * 4;                 // 83,072 B
    const int smemB = (128 * 129 + 128 * 64) * 4;           // 98,816 B
    cudaFuncSetAttribute(attn_kernel, cudaFuncAttributeMaxDynamicSharedMemorySize, smemA);
    cudaFuncSetAttribute(gemm_kernel, cudaFuncAttributeMaxDynamicSharedMemorySize, smemB);

    const int gblocks = (N + 127) / 128;

    // tiny vector fold (runs concurrently-ish at wave tail of nothing; ~1-2us)
    w2a_kernel<<<1, 128>>>(W2, a);

    // x = input @ W -> out[:, 0:64]
    gemm_kernel<<<gblocks, 128, smemB>>>(input, W, a, out, N, 0, 0, 0);

    // attention + aggregation (reads out[:,0:64] for the x-score term)
    attn_kernel<<<(N + 7) / 8, 256, smemA>>>(neigh, edge, a, out, N);

    // h_prime = g_agg @ W2 -> out[:, 64:128]
    gemm_kernel<<<gblocks, 128, smemB>>>(nullptr, W2, a, out, N, 64, 1, 0);
}